// round 2
// baseline (speedup 1.0000x reference)
#include <cuda_runtime.h>

// Problem constants
#define BATCH   1024
#define IN_H    128
#define IN_W    128
#define HPAD    132      // IN_H + 2*2
#define WPAD    132
#define NKH     25
#define NKW     25
#define NK      625
#define KHW     100      // 10*10

// Tiling
#define IGROUPS 5        // blockIdx.y: groups of 5 output rows
#define KL      125      // outputs per block (5 rows * 25 cols)
#define WSTR    101      // weight smem row stride (101 mod 32 = 5 -> conflict-free)
#define XROWS   30       // x rows staged per image (5 output rows span 30 input rows incl. pad)
#define XS      152      // x smem row stride in words: 152 mod 32 = 24 (<=1 two-way conflict), mult of 4 (aligned f4 stores)
#define NB      8        // images staged per group
#define BSPLIT  29       // blockIdx.x: batch stripes (5*29 = 145 blocks ~ one wave)

// Extracted weights: g_w[k*100 + dy*10 + dx]
__device__ float g_w[NK * KHW];

// ---------------------------------------------------------------------------
// Kernel 1: gather the 62,500 live weights out of the dense [17424 x 625] W.
// W[((ki*5+dy)*132 + kj*5+dx) * 625 + k] == kernel_weights[k, dy, dx]
// ---------------------------------------------------------------------------
__global__ void extract_kernel(const float* __restrict__ W)
{
    int idx = blockIdx.x * blockDim.x + threadIdx.x;
    if (idx >= NK * KHW) return;
    int k  = idx / KHW;
    int d  = idx - k * KHW;
    int dy = d / 10;
    int dx = d - dy * 10;
    int ki = k / NKW;
    int kj = k - ki * NKW;
    int r  = (ki * 5 + dy) * WPAD + (kj * 5 + dx);
    g_w[idx] = W[(size_t)r * NK + k];
}

// ---------------------------------------------------------------------------
// Kernel 2: locally-connected conv with weights resident in SMEM.
//   grid = (BSPLIT, IGROUPS), block = 256
//   block (bx, ig): outputs rows i in [ig*5, ig*5+5), batches b = bx + t*29
// SMEM layout (floats):
//   ws [12640]  : 125 x 100 weights, stride 101
//   xs [36480]  : NB * 30 * 152 staged x rows; x col c of row lives at +4+c,
//                 padded col cc reads at +2+cc (zeros at +2,+3,+132,+133)
//   bs [128]    : bias for this block's 125 outputs
// ---------------------------------------------------------------------------
#define WS_FLOATS  12640
#define XS_FLOATS  (NB * XROWS * XS)   // 36480
#define SMEM_FLOATS (WS_FLOATS + XS_FLOATS + 128)
#define SMEM_BYTES  (SMEM_FLOATS * 4)  // 196,992 B

__global__ __launch_bounds__(256, 1)
void lc2d_kernel(const float* __restrict__ x,
                 const float* __restrict__ bias,
                 float* __restrict__ out)
{
    extern __shared__ float sm[];
    float* ws = sm;
    float* xs = sm + WS_FLOATS;
    float* bs = sm + WS_FLOATS + XS_FLOATS;

    const int bx  = blockIdx.x;   // 0..28
    const int ig  = blockIdx.y;   // 0..4
    const int tid = threadIdx.x;  // 0..255

    // ---- stage this block's weights (50 KB) into SMEM, vectorized ----
    const float* gw = g_w + ig * (KL * KHW);        // 50000 B offset: 16B aligned
    for (int i4 = tid; i4 < (KL * KHW) / 4; i4 += 256) {
        float4 v = reinterpret_cast<const float4*>(gw)[i4];
        int idx = i4 * 4;
        int kl  = idx / KHW;
        int d   = idx - kl * KHW;                   // multiple of 4, stays in-row
        float* p = &ws[kl * WSTR + d];
        p[0] = v.x; p[1] = v.y; p[2] = v.z; p[3] = v.w;
    }
    if (tid < KL) bs[tid] = bias[ig * KL + tid];

    const int r0       = ig * 25 - 2;               // first input row (may be <0)
    const int nb_total = (BATCH - 1 - bx) / BSPLIT + 1;

    const int half = tid >> 7;                      // 0: bl 0..3, 1: bl 4..7
    const int kl   = tid & 127;
    const int il   = kl / 25;
    const int jj   = kl - il * 25;

    for (int g0 = 0; g0 < nb_total; g0 += NB) {
        __syncthreads();   // previous compute done before overwriting xs

        // ---- stage NB image tiles: rows r0..r0+29, 128 cols each ----
        for (int idx = tid; idx < NB * XROWS * 32; idx += 256) {
            int bl  = idx / (XROWS * 32);
            int rem = idx - bl * (XROWS * 32);
            int rr  = rem >> 5;
            int c4  = rem & 31;
            float4 v = make_float4(0.f, 0.f, 0.f, 0.f);
            int r = r0 + rr;
            int t = g0 + bl;
            if (t < nb_total && r >= 0 && r < IN_H) {
                int b = bx + t * BSPLIT;
                v = reinterpret_cast<const float4*>(x + (size_t)b * (IN_H * IN_W) + r * IN_W)[c4];
            }
            // row start word-index is mult of 4; +4 keeps 16B alignment
            reinterpret_cast<float4*>(&xs[bl * (XROWS * XS) + rr * XS + 4])[c4] = v;
        }
        // zero the 2-col left/right halo (padded cols -2,-1 and 128,129)
        for (int idx = tid; idx < NB * XROWS; idx += 256) {
            int bl = idx / XROWS;
            int rr = idx - bl * XROWS;
            float* p = &xs[bl * (XROWS * XS) + rr * XS];
            p[2] = 0.f; p[3] = 0.f; p[132] = 0.f; p[133] = 0.f;
        }
        __syncthreads();

        // ---- compute: each thread = 1 output k, 4 images ----
        if (kl < KL) {
            const float* wp = ws + kl * WSTR;
            // padded col cc lives at row-offset 2+cc; window col base = jj*5
            const float* xp = xs + half * (4 * XROWS * XS) + (il * 5) * XS + jj * 5 + 2;
            float a0 = 0.f, a1 = 0.f, a2 = 0.f, a3 = 0.f;
            #pragma unroll
            for (int dy = 0; dy < 10; ++dy) {
                #pragma unroll
                for (int dx = 0; dx < 10; ++dx) {
                    float w = wp[dy * 10 + dx];
                    int   o = dy * XS + dx;
                    a0 = fmaf(xp[o                 ], w, a0);
                    a1 = fmaf(xp[o +     XROWS * XS], w, a1);
                    a2 = fmaf(xp[o + 2 * XROWS * XS], w, a2);
                    a3 = fmaf(xp[o + 3 * XROWS * XS], w, a3);
                }
            }
            float bv = bs[kl];
            int   tb = g0 + half * 4;
            int   ob = ig * KL + kl;
            if (tb + 0 < nb_total) out[(size_t)(bx + (tb + 0) * BSPLIT) * NK + ob] = a0 + bv;
            if (tb + 1 < nb_total) out[(size_t)(bx + (tb + 1) * BSPLIT) * NK + ob] = a1 + bv;
            if (tb + 2 < nb_total) out[(size_t)(bx + (tb + 2) * BSPLIT) * NK + ob] = a2 + bv;
            if (tb + 3 < nb_total) out[(size_t)(bx + (tb + 3) * BSPLIT) * NK + ob] = a3 + bv;
        }
    }
}

// ---------------------------------------------------------------------------
extern "C" void kernel_launch(void* const* d_in, const int* in_sizes, int n_in,
                              void* d_out, int out_size)
{
    const float* x    = (const float*)d_in[0];   // [1024,128,128]
    const float* W    = (const float*)d_in[1];   // [17424,625]
    const float* bias = (const float*)d_in[2];   // [25,25]
    float* out = (float*)d_out;                  // [1024,25,25]

    cudaFuncSetAttribute(lc2d_kernel,
                         cudaFuncAttributeMaxDynamicSharedMemorySize, SMEM_BYTES);

    extract_kernel<<<(NK * KHW + 255) / 256, 256>>>(W);

    dim3 grid(BSPLIT, IGROUPS);
    lc2d_kernel<<<grid, 256, SMEM_BYTES>>>(x, bias, out);
}

// round 4
// speedup vs baseline: 1.3047x; 1.3047x over previous
#include <cuda_runtime.h>
#include <cstdint>

// Problem constants
#define BATCH   1024
#define IN_H    128
#define IN_W    128
#define WPAD    132
#define NKW     25
#define NK      625
#define KHW     100

// Tiling
#define IGROUPS 5          // blockIdx.y: groups of 5 output rows
#define KL      125        // outputs per block (5 rows * 25 cols)
#define XROWS   30         // padded input rows needed per 5 output rows
#define XS      152        // x smem row stride (words): conflict-light, mult of 4
#define IMGW    (XROWS*XS) // 4560 words per image tile
#define HB      4          // images per half-buffer
#define HBW     (HB*IMGW)  // 18240
#define BSPLIT  29         // batch stripes: 29*5 = 145 blocks ~= one wave
#define SMEM_BYTES (2*HBW*4)  // 145,920 B (double-buffered x only)

// Extracted weights: g_w[k*100 + dy*10 + dx]
__device__ float g_w[NK * KHW];

// ---------------------------------------------------------------------------
// Gather the 62,500 live weights out of dense W [17424 x 625].
// W[((ki*5+dy)*132 + kj*5+dx) * 625 + k] == kernel_weights[k, dy, dx]
// ---------------------------------------------------------------------------
__global__ void extract_kernel(const float* __restrict__ W)
{
    int idx = blockIdx.x * blockDim.x + threadIdx.x;
    if (idx >= NK * KHW) return;
    int k  = idx / KHW;
    int d  = idx - k * KHW;
    int dy = d / 10;
    int dx = d - dy * 10;
    int ki = k / NKW;
    int kj = k - ki * NKW;
    int r  = (ki * 5 + dy) * WPAD + (kj * 5 + dx);
    g_w[idx] = W[(size_t)r * NK + k];
}

// ---------------------------------------------------------------------------
// Main kernel: weights register-resident, x double-buffered via cp.async.
// grid=(29,5), block=256. Thread (h=tid>>7, kl=tid&127) computes output kl
// for 2 images per 4-image half-buffer.
// x layout per image: row rr at word rr*XS; padded col cc at word 2+cc.
// cp.async fills words [4,131] (the 128 real cols); halo words 2,3,132,133
// are zeroed once (cp.async never touches them).
// ---------------------------------------------------------------------------
__device__ __forceinline__ void cp16(unsigned int dst_smem, const float* src, int src_sz)
{
    asm volatile("cp.async.cg.shared.global [%0], [%1], 16, %2;\n"
                 :: "r"(dst_smem), "l"(src), "r"(src_sz));
}

__global__ __launch_bounds__(256, 1)
void lc2d_kernel(const float* __restrict__ x,
                 const float* __restrict__ bias,
                 float* __restrict__ out)
{
    extern __shared__ float xs[];
    const unsigned int xs_base = (unsigned int)__cvta_generic_to_shared(xs);

    const int bx  = blockIdx.x;   // 0..28
    const int ig  = blockIdx.y;   // 0..4
    const int tid = threadIdx.x;

    // ---- zero halo columns once (240 rows x 4 words) ----
    for (int idx = tid; idx < 2 * HB * XROWS; idx += 256) {
        float* p = &xs[idx * XS];
        p[2] = 0.f; p[3] = 0.f; p[132] = 0.f; p[133] = 0.f;
    }

    const int kl = tid & 127;
    const int h  = tid >> 7;
    const int klc = kl < KL ? kl : KL - 1;

    // ---- weights into registers (loop-invariant across whole batch loop) ----
    float4 w4[25];
    {
        const float4* wg = reinterpret_cast<const float4*>(g_w) + (ig * KL + klc) * 25;
        #pragma unroll
        for (int j = 0; j < 25; ++j) w4[j] = __ldg(&wg[j]);
    }
    const float bv = __ldg(&bias[ig * KL + klc]);

    const int r0       = ig * 25 - 2;
    const int nb_total = (BATCH - 1 - bx) / BSPLIT + 1;   // 35 or 36
    const int NH       = (nb_total + HB - 1) / HB;        // 9

    const int il = klc / 25;
    const int jj = klc - il * 25;
    const int xoff = (il * 5) * XS + jj * 5 + 2;

    // ---- fill one half-buffer (4 images) for half-group hg ----
    auto fill = [&](int buf, int hg) {
        #pragma unroll
        for (int i = 0; i < 15; ++i) {
            int idx = tid + i * 256;              // < 3840
            int bl  = idx / (XROWS * 32);
            int rem = idx - bl * (XROWS * 32);
            int rr  = rem >> 5;
            int c4  = rem & 31;
            int t   = hg * HB + bl;
            int r   = r0 + rr;
            bool v  = (t < nb_total) & (r >= 0) & (r < IN_H);
            const float* src = v
                ? x + (size_t)(bx + t * BSPLIT) * (IN_H * IN_W) + r * IN_W + c4 * 4
                : x;                               // clamped, src_sz=0 -> zfill
            unsigned int dst = xs_base +
                (unsigned int)(buf * HBW + bl * IMGW + rr * XS + 4 + c4 * 4) * 4u;
            cp16(dst, src, v ? 16 : 0);
        }
        asm volatile("cp.async.commit_group;\n");
    };

    // prologue: fill both buffers
    fill(0, 0);
    fill(1, 1);

    for (int g = 0; g < NH; ++g) {
        if (g == NH - 1) asm volatile("cp.async.wait_group 0;\n");
        else             asm volatile("cp.async.wait_group 1;\n");
        __syncthreads();

        const int buf = g & 1;
        if (kl < KL) {
            const float* xpA = xs + buf * HBW + (2 * h) * IMGW + xoff;
            const float* xpB = xpA + IMGW;
            float a0 = 0.f, a1 = 0.f;
            const float* wf = reinterpret_cast<const float*>(w4);
            #pragma unroll
            for (int dy = 0; dy < 10; ++dy) {
                #pragma unroll
                for (int dx = 0; dx < 10; ++dx) {
                    float w = wf[dy * 10 + dx];
                    int   o = dy * XS + dx;
                    a0 = fmaf(xpA[o], w, a0);
                    a1 = fmaf(xpB[o], w, a1);
                }
            }
            int tA = g * HB + 2 * h;
            int ob = ig * KL + kl;
            if (tA < nb_total)
                out[(size_t)(bx + tA * BSPLIT) * NK + ob] = a0 + bv;
            if (tA + 1 < nb_total)
                out[(size_t)(bx + (tA + 1) * BSPLIT) * NK + ob] = a1 + bv;
        }
        __syncthreads();

        if (g + 2 < NH) fill(buf, g + 2);
    }
}

// ---------------------------------------------------------------------------
extern "C" void kernel_launch(void* const* d_in, const int* in_sizes, int n_in,
                              void* d_out, int out_size)
{
    const float* x    = (const float*)d_in[0];   // [1024,128,128]
    const float* W    = (const float*)d_in[1];   // [17424,625]
    const float* bias = (const float*)d_in[2];   // [25,25]
    float* out = (float*)d_out;                  // [1024,25,25]

    cudaFuncSetAttribute(lc2d_kernel,
                         cudaFuncAttributeMaxDynamicSharedMemorySize, SMEM_BYTES);

    extract_kernel<<<(NK * KHW + 255) / 256, 256>>>(W);

    dim3 grid(BSPLIT, IGROUPS);
    lc2d_kernel<<<grid, 256, SMEM_BYTES>>>(x, bias, out);
}